// round 10
// baseline (speedup 1.0000x reference)
#include <cuda_runtime.h>

// VDEmbedding: out[t, :] = mask[x[t]] * weight[x[t], :], zero at pad (idx==0).
// x: [65536] int64 OR int32 (auto-detected), weight: [128000,128] f32,
// mask: [128000] f32, out: [65536,128] f32.
//
// R8: LTS-ceiling polish of the R7 winner. Aggregate L2 traffic (~68MB) over
// the measured ~6.3TB/s LTS cap puts the floor at ~10.6us; this round only
// shaves issue/queue overhead: mask loads issued before the 512B gathers
// (tiny loads overlap instead of queueing behind them), 32-bit gather index
// arithmetic, warp-uniform dtype branch kept (branchless would add traffic).

#define EMBED_V4 32     // 128 floats = 32 float4 per row
#define TOK_PER_WARP 4
#define THREADS 128

__global__ __launch_bounds__(THREADS) void vdembed_kernel(
    const unsigned int* __restrict__ x32,  // raw index words (i32 or i64 layout)
    const float4*       __restrict__ w4,   // weight as [V, 32] float4
    const float*        __restrict__ mask,
    float4*             __restrict__ out4, // out as [T, 32] float4
    int n_tokens)
{
    const int lane = threadIdx.x & 31;
    const int warp = (int)((blockIdx.x * blockDim.x + threadIdx.x) >> 5);
    const int t0   = warp * TOK_PER_WARP;
    if (t0 >= n_tokens) return;

    // ---- concurrent: dtype probe + speculative i32 index load ----
    // int64 data => all odd 32-bit words zero; int32 => odd words are random
    // token ids (P(32 zeros) ~ (1/128000)^32 ~ 0). 256B, L1-broadcast-hot.
    // The uint4 load at word offset t0 is in-bounds for BOTH layouts.
    unsigned int probe = x32[2 * lane + 1];
    const uint4* xi = (const uint4*)x32;
    uint4 a32 = __ldg(&xi[t0 >> 2]);

    probe = __reduce_or_sync(0xffffffffu, probe);

    unsigned int id[TOK_PER_WARP];
    if (probe == 0u) {   // int64 layout
        const ulonglong2* xl = (const ulonglong2*)x32;
        ulonglong2 a = __ldg(&xl[(t0 >> 1) + 0]);  // tokens t0, t0+1
        ulonglong2 b = __ldg(&xl[(t0 >> 1) + 1]);  // tokens t0+2, t0+3
        id[0] = (unsigned int)a.x; id[1] = (unsigned int)a.y;
        id[2] = (unsigned int)b.x; id[3] = (unsigned int)b.y;
    } else {             // int32 layout
        id[0] = a32.x; id[1] = a32.y; id[2] = a32.z; id[3] = a32.w;
    }

    // ---- 4 tiny scale loads FIRST (overlap under the big gathers) ----
    float sc[TOK_PER_WARP];
#pragma unroll
    for (int t = 0; t < TOK_PER_WARP; t++)
        sc[t] = (id[t] == 0u) ? 0.0f : __ldg(&mask[id[t]]);

    // ---- 4 independent 512B row gathers (32-bit address math) ----
    float4 v[TOK_PER_WARP];
#pragma unroll
    for (int t = 0; t < TOK_PER_WARP; t++) {
        const unsigned int off = id[t] * (unsigned)EMBED_V4 + (unsigned)lane;
        v[t] = __ldg(w4 + off);
    }

    // ---- scale + streaming store, each token as soon as it's ready ----
    float4* o = out4 + (size_t)t0 * EMBED_V4 + lane;
#pragma unroll
    for (int t = 0; t < TOK_PER_WARP; t++) {
        v[t].x *= sc[t]; v[t].y *= sc[t]; v[t].z *= sc[t]; v[t].w *= sc[t];
        __stcs(o + (size_t)t * EMBED_V4, v[t]);
    }
}

extern "C" void kernel_launch(void* const* d_in, const int* in_sizes, int n_in,
                              void* d_out, int out_size) {
    const unsigned int* x   = (const unsigned int*)d_in[0]; // [B*S] i64 or i32
    const float*        w   = (const float*)d_in[1];        // [V, 128]
    const float*        msk = (const float*)d_in[2];        // [V]
    float*              out = (float*)d_out;                // [B*S, 128]

    const int n_tokens = in_sizes[0];
    const int warps    = (n_tokens + TOK_PER_WARP - 1) / TOK_PER_WARP;
    const int blocks   = (warps * 32 + THREADS - 1) / THREADS;

    vdembed_kernel<<<blocks, THREADS>>>(
        x, (const float4*)w, msk, (float4*)out, n_tokens);
}

// round 11
// speedup vs baseline: 1.0087x; 1.0087x over previous
#include <cuda_runtime.h>

// VDEmbedding: out[t, :] = mask[x[t]] * weight[x[t], :], zero at pad (idx==0).
// x: [65536] int64 OR int32 (auto-detected), weight: [128000,128] f32,
// mask: [128000] f32, out: [65536,128] f32.
//
// R9: exact R6 winner (10.72us) with ONE change: normal write-back stores
// instead of __stcs. Warm working set = 65.5MB table + 33.5MB output + idx
// = ~99.5MB < 126MB L2, so under graph replay the output lines stay L2-
// resident and are overwritten in place -- the DRAM write stream drops off
// the critical path. Stores are full-line 512B/warp (no write-allocate
// fetch). Single-variable A/B against the streaming-store hypothesis.

#define EMBED_V4 32     // 128 floats = 32 float4 per row
#define TOK_PER_WARP 4
#define THREADS 128

__global__ __launch_bounds__(THREADS) void vdembed_kernel(
    const unsigned int* __restrict__ x32,  // raw index words (i32 or i64 layout)
    const float4*       __restrict__ w4,   // weight as [V, 32] float4
    const float*        __restrict__ mask,
    float4*             __restrict__ out4, // out as [T, 32] float4
    int n_tokens)
{
    const int lane = threadIdx.x & 31;
    const int warp = (int)((blockIdx.x * blockDim.x + threadIdx.x) >> 5);
    const int t0   = warp * TOK_PER_WARP;
    if (t0 >= n_tokens) return;

    // ---- issue concurrently: dtype probe + speculative i32 index load ----
    // int64 data => all odd 32-bit words zero; int32 => odd words are random
    // token ids (P(32 zeros) ~ (1/128000)^32 ~ 0). 256B, L1-broadcast-hot.
    // The uint4 load at word offset t0 is in-bounds for BOTH layouts.
    unsigned int probe = x32[2 * lane + 1];
    const uint4* xi = (const uint4*)x32;
    uint4 a32 = __ldg(&xi[t0 >> 2]);               // speculative i32 indices

    probe = __reduce_or_sync(0xffffffffu, probe);
    const bool is_i64 = (probe == 0u);

    unsigned int id[TOK_PER_WARP];
    if (is_i64) {
        const ulonglong2* xl = (const ulonglong2*)x32;
        ulonglong2 a = __ldg(&xl[(t0 >> 1) + 0]);  // tokens t0, t0+1
        ulonglong2 b = __ldg(&xl[(t0 >> 1) + 1]);  // tokens t0+2, t0+3
        id[0] = (unsigned int)a.x; id[1] = (unsigned int)a.y;
        id[2] = (unsigned int)b.x; id[3] = (unsigned int)b.y;
    } else {
        id[0] = a32.x; id[1] = a32.y; id[2] = a32.z; id[3] = a32.w;
    }

    // ---- 4 independent 512B row gathers in flight (gathers FIRST: the
    //      R6-vs-R8 A/B showed this ordering is faster) ----
    float4 v[TOK_PER_WARP];
#pragma unroll
    for (int t = 0; t < TOK_PER_WARP; t++)
        v[t] = __ldg(&w4[(size_t)id[t] * EMBED_V4 + lane]);

    // ---- 4 independent scale loads (overlap the gathers) ----
    float sc[TOK_PER_WARP];
#pragma unroll
    for (int t = 0; t < TOK_PER_WARP; t++)
        sc[t] = (id[t] == 0u) ? 0.0f : __ldg(&mask[id[t]]);

    // ---- scale + normal write-back store (output stays L2-resident and is
    //      rewritten in place across graph replays) ----
    float4* o = out4 + (size_t)t0 * EMBED_V4 + lane;
#pragma unroll
    for (int t = 0; t < TOK_PER_WARP; t++) {
        v[t].x *= sc[t]; v[t].y *= sc[t]; v[t].z *= sc[t]; v[t].w *= sc[t];
        o[(size_t)t * EMBED_V4] = v[t];
    }
}

extern "C" void kernel_launch(void* const* d_in, const int* in_sizes, int n_in,
                              void* d_out, int out_size) {
    const unsigned int* x   = (const unsigned int*)d_in[0]; // [B*S] i64 or i32
    const float*        w   = (const float*)d_in[1];        // [V, 128]
    const float*        msk = (const float*)d_in[2];        // [V]
    float*              out = (float*)d_out;                // [B*S, 128]

    const int n_tokens = in_sizes[0];
    const int warps    = (n_tokens + TOK_PER_WARP - 1) / TOK_PER_WARP;
    const int blocks   = (warps * 32 + THREADS - 1) / THREADS;

    vdembed_kernel<<<blocks, THREADS>>>(
        x, (const float4*)w, msk, (float4*)out, n_tokens);
}